// round 2
// baseline (speedup 1.0000x reference)
#include <cuda_runtime.h>
#include <mma.h>

using namespace nvcuda;

// Problem dims (fixed)
#define DMODEL 1024
#define NH     16
#define DH     64
#define BATCH  4
#define SEQ    1024
#define BH     (BATCH*NH)          // 64

// Scratch (static device globals; no runtime allocation allowed)
__device__ float g_q  [(size_t)BATCH*SEQ*DMODEL];     // [b, i, h*64+d]  (16 MB)
__device__ float g_k  [(size_t)BATCH*SEQ*DH];         // [b, j, d]       (1 MB)
__device__ float g_v  [(size_t)BATCH*SEQ*DH];         // [b, j, d]       (1 MB)
__device__ float g_s  [(size_t)BH*SEQ*SEQ];           // [bh, i, j]      (268 MB)
__device__ float g_ctx[(size_t)BATCH*SEQ*DMODEL];     // [b, i, h*64+d]  (16 MB)

// ---------------------------------------------------------------------------
// 64x64 output tile, NT GEMM (C = A * B^T), tf32 wmma, fp32 accumulate.
// A: rows at A, row-major, lda.  B: rows at B (these are C's columns), ldb.
// C at (0,0) of the tile, row stride ldc. 128 threads (4 warps, 2x2).
// ---------------------------------------------------------------------------
__device__ __forceinline__ void tile_gemm_nt_64(
    const float* __restrict__ A, int lda,
    const float* __restrict__ B, int ldb,
    float* __restrict__ C, size_t ldc,
    int K, bool accum)
{
    __shared__ float As[64][36];
    __shared__ float Bs[64][36];
    const int tid  = threadIdx.x;
    const int warp = tid >> 5;
    const int wm   = warp >> 1;     // 0..1
    const int wn   = warp & 1;      // 0..1

    wmma::fragment<wmma::accumulator, 16, 16, 8, float> cf[2][2];
    #pragma unroll
    for (int mi = 0; mi < 2; ++mi)
        #pragma unroll
        for (int ni = 0; ni < 2; ++ni) {
            if (accum)
                wmma::load_matrix_sync(cf[mi][ni],
                    C + (size_t)(wm*32 + mi*16)*ldc + (wn*32 + ni*16),
                    (unsigned)ldc, wmma::mem_row_major);
            else
                wmma::fill_fragment(cf[mi][ni], 0.0f);
        }

    for (int k0 = 0; k0 < K; k0 += 32) {
        // Stage 64x32 tiles of A and B into smem, rounding to tf32.
        #pragma unroll
        for (int it = 0; it < 4; ++it) {
            int e = tid + it*128;            // 0..511 float4 slots
            int r = e >> 3;                  // 0..63
            int c = (e & 7) * 4;             // 0,4,...,28
            float4 va = *reinterpret_cast<const float4*>(A + (size_t)r*lda + k0 + c);
            As[r][c+0] = wmma::__float_to_tf32(va.x);
            As[r][c+1] = wmma::__float_to_tf32(va.y);
            As[r][c+2] = wmma::__float_to_tf32(va.z);
            As[r][c+3] = wmma::__float_to_tf32(va.w);
            float4 vb = *reinterpret_cast<const float4*>(B + (size_t)r*ldb + k0 + c);
            Bs[r][c+0] = wmma::__float_to_tf32(vb.x);
            Bs[r][c+1] = wmma::__float_to_tf32(vb.y);
            Bs[r][c+2] = wmma::__float_to_tf32(vb.z);
            Bs[r][c+3] = wmma::__float_to_tf32(vb.w);
        }
        __syncthreads();

        #pragma unroll
        for (int kf = 0; kf < 4; ++kf) {
            wmma::fragment<wmma::matrix_a, 16, 16, 8, wmma::precision::tf32, wmma::row_major> af[2];
            wmma::fragment<wmma::matrix_b, 16, 16, 8, wmma::precision::tf32, wmma::col_major> bf[2];
            #pragma unroll
            for (int mi = 0; mi < 2; ++mi)
                wmma::load_matrix_sync(af[mi], &As[wm*32 + mi*16][kf*8], 36);
            #pragma unroll
            for (int ni = 0; ni < 2; ++ni)
                wmma::load_matrix_sync(bf[ni], &Bs[wn*32 + ni*16][kf*8], 36);
            #pragma unroll
            for (int mi = 0; mi < 2; ++mi)
                #pragma unroll
                for (int ni = 0; ni < 2; ++ni)
                    wmma::mma_sync(cf[mi][ni], af[mi], bf[ni], cf[mi][ni]);
        }
        __syncthreads();
    }

    #pragma unroll
    for (int mi = 0; mi < 2; ++mi)
        #pragma unroll
        for (int ni = 0; ni < 2; ++ni)
            wmma::store_matrix_sync(
                C + (size_t)(wm*32 + mi*16)*ldc + (wn*32 + ni*16),
                cf[mi][ni], (unsigned)ldc, wmma::mem_row_major);
}

// ---------------------------------------------------------------------------
// Generic NT GEMM: C[M,N] = A[M,K] * B[N,K]^T  (grid.x = M/64, grid.y = N/64)
// ---------------------------------------------------------------------------
__global__ void gemm_nt(const float* __restrict__ A, int lda,
                        const float* __restrict__ B, int ldb,
                        float* __restrict__ C, int ldc, int K)
{
    size_t row0 = (size_t)blockIdx.x * 64;
    size_t col0 = (size_t)blockIdx.y * 64;
    tile_gemm_nt_64(A + row0*lda, lda, B + col0*ldb, ldb,
                    C + row0*ldc + col0, (size_t)ldc, K, false);
}

// ---------------------------------------------------------------------------
// c2c: scores[bh,i,j] = sum_d q[b,i,h*64+d] * k[b,j,d]
// grid: (j_tiles=16, i_tiles=16, bh=64)
// ---------------------------------------------------------------------------
__global__ void c2c_kernel()
{
    const int bh = blockIdx.z;
    const int b  = bh >> 4;
    const int h  = bh & 15;
    size_t i0 = (size_t)blockIdx.y * 64;
    size_t j0 = (size_t)blockIdx.x * 64;
    const float* A = g_q + ((size_t)b*SEQ + i0)*DMODEL + h*DH;   // lda = DMODEL
    const float* B = g_k + (size_t)b*SEQ*DH + j0*DH;             // ldb = DH
    float*       C = g_s + (size_t)bh*SEQ*SEQ + i0*SEQ + j0;     // ldc = SEQ
    tile_gemm_nt_64(A, DMODEL, B, DH, C, (size_t)SEQ, DH, false);
}

// ---------------------------------------------------------------------------
// c2p: scores[bh,i,j] += q[b,i,h*64+:] . rel[i,j,:]
// For fixed i this is a GEMM: Q_i[64bh x 64d] * rel[i][64j x 64d]^T.
// grid: (j_tiles=16, i=1024). Accumulates into g_s (RMW).
// ---------------------------------------------------------------------------
__global__ void c2p_kernel(const float* __restrict__ rel)
{
    const int i  = blockIdx.y;
    size_t j0 = (size_t)blockIdx.x * 64;

    __shared__ float As[64][68];   // rows = bh, cols = d
    __shared__ float Bs[64][68];   // rows = local j, cols = d

    const int tid  = threadIdx.x;
    const int warp = tid >> 5;
    const int wm   = warp >> 1;
    const int wn   = warp & 1;

    // Stage A (gathered Q_i rows) and B (rel slice), tf32-rounded.
    #pragma unroll
    for (int it = 0; it < 8; ++it) {
        int e = tid + it*128;        // 0..1023 float4 slots
        int r = e >> 4;              // 0..63
        int c = (e & 15) * 4;        // 0..60
        int b = r >> 4, h = r & 15;
        float4 va = *reinterpret_cast<const float4*>(
            g_q + ((size_t)b*SEQ + i)*DMODEL + h*DH + c);
        As[r][c+0] = wmma::__float_to_tf32(va.x);
        As[r][c+1] = wmma::__float_to_tf32(va.y);
        As[r][c+2] = wmma::__float_to_tf32(va.z);
        As[r][c+3] = wmma::__float_to_tf32(va.w);
        float4 vb = *reinterpret_cast<const float4*>(
            rel + ((size_t)i*SEQ + j0 + r)*DH + c);
        Bs[r][c+0] = wmma::__float_to_tf32(vb.x);
        Bs[r][c+1] = wmma::__float_to_tf32(vb.y);
        Bs[r][c+2] = wmma::__float_to_tf32(vb.z);
        Bs[r][c+3] = wmma::__float_to_tf32(vb.w);
    }
    __syncthreads();

    float* C = g_s + (size_t)i*SEQ + j0;        // row stride (per bh) = SEQ*SEQ
    const size_t ldc = (size_t)SEQ*SEQ;

    wmma::fragment<wmma::accumulator, 16, 16, 8, float> cf[2][2];
    #pragma unroll
    for (int mi = 0; mi < 2; ++mi)
        #pragma unroll
        for (int ni = 0; ni < 2; ++ni)
            wmma::load_matrix_sync(cf[mi][ni],
                C + (size_t)(wm*32 + mi*16)*ldc + (wn*32 + ni*16),
                (unsigned)ldc, wmma::mem_row_major);

    #pragma unroll
    for (int kf = 0; kf < 8; ++kf) {
        wmma::fragment<wmma::matrix_a, 16, 16, 8, wmma::precision::tf32, wmma::row_major> af[2];
        wmma::fragment<wmma::matrix_b, 16, 16, 8, wmma::precision::tf32, wmma::col_major> bf[2];
        #pragma unroll
        for (int mi = 0; mi < 2; ++mi)
            wmma::load_matrix_sync(af[mi], &As[wm*32 + mi*16][kf*8], 68);
        #pragma unroll
        for (int ni = 0; ni < 2; ++ni)
            wmma::load_matrix_sync(bf[ni], &Bs[wn*32 + ni*16][kf*8], 68);
        #pragma unroll
        for (int mi = 0; mi < 2; ++mi)
            #pragma unroll
            for (int ni = 0; ni < 2; ++ni)
                wmma::mma_sync(cf[mi][ni], af[mi], bf[ni], cf[mi][ni]);
    }

    #pragma unroll
    for (int mi = 0; mi < 2; ++mi)
        #pragma unroll
        for (int ni = 0; ni < 2; ++ni)
            wmma::store_matrix_sync(
                C + (size_t)(wm*32 + mi*16)*ldc + (wn*32 + ni*16),
                cf[mi][ni], (unsigned)ldc, wmma::mem_row_major);
}

// ---------------------------------------------------------------------------
// Softmax over last dim (1024) with scale 1/8. One warp per row, 8 rows/block.
// ---------------------------------------------------------------------------
__global__ void softmax_kernel()
{
    const int warp = threadIdx.x >> 5;
    const int lane = threadIdx.x & 31;
    const size_t row = (size_t)blockIdx.x * 8 + warp;   // 0 .. 65535
    float* p = g_s + row * SEQ;

    float4 v[8];
    float m = -1e30f;
    #pragma unroll
    for (int t = 0; t < 8; ++t) {
        v[t] = reinterpret_cast<const float4*>(p)[t*32 + lane];
        v[t].x *= 0.125f; v[t].y *= 0.125f; v[t].z *= 0.125f; v[t].w *= 0.125f;
        m = fmaxf(m, fmaxf(fmaxf(v[t].x, v[t].y), fmaxf(v[t].z, v[t].w)));
    }
    #pragma unroll
    for (int off = 16; off > 0; off >>= 1)
        m = fmaxf(m, __shfl_xor_sync(0xffffffffu, m, off));

    float sum = 0.0f;
    #pragma unroll
    for (int t = 0; t < 8; ++t) {
        v[t].x = __expf(v[t].x - m);
        v[t].y = __expf(v[t].y - m);
        v[t].z = __expf(v[t].z - m);
        v[t].w = __expf(v[t].w - m);
        sum += v[t].x + v[t].y + v[t].z + v[t].w;
    }
    #pragma unroll
    for (int off = 16; off > 0; off >>= 1)
        sum += __shfl_xor_sync(0xffffffffu, sum, off);

    const float inv = __fdividef(1.0f, sum);
    #pragma unroll
    for (int t = 0; t < 8; ++t) {
        v[t].x *= inv; v[t].y *= inv; v[t].z *= inv; v[t].w *= inv;
        reinterpret_cast<float4*>(p)[t*32 + lane] = v[t];
    }
}

// ---------------------------------------------------------------------------
// AV: ctx[b,i,h*64+d] = sum_j attn[bh,i,j] * v[b,j,d]   (NN GEMM per bh)
// grid: (i_tiles=16, 1, bh=64)
// ---------------------------------------------------------------------------
__global__ void av_kernel()
{
    const int bh = blockIdx.z;
    const int b  = bh >> 4;
    const int h  = bh & 15;
    size_t i0 = (size_t)blockIdx.x * 64;

    const float* A = g_s + (size_t)bh*SEQ*SEQ + i0*SEQ;          // lda = SEQ
    const float* B = g_v + (size_t)b*SEQ*DH;                     // [j][d], ldb = DH
    float*       C = g_ctx + ((size_t)b*SEQ + i0)*DMODEL + h*DH; // ldc = DMODEL

    __shared__ float As[64][36];   // [i-local][k-local]
    __shared__ float Bs[32][68];   // [k-local][d]

    const int tid  = threadIdx.x;
    const int warp = tid >> 5;
    const int wm   = warp >> 1;
    const int wn   = warp & 1;

    wmma::fragment<wmma::accumulator, 16, 16, 8, float> cf[2][2];
    #pragma unroll
    for (int mi = 0; mi < 2; ++mi)
        #pragma unroll
        for (int ni = 0; ni < 2; ++ni)
            wmma::fill_fragment(cf[mi][ni], 0.0f);

    for (int k0 = 0; k0 < SEQ; k0 += 32) {
        #pragma unroll
        for (int it = 0; it < 4; ++it) {
            int e = tid + it*128;            // A: 512 float4 slots (64x32)
            int r = e >> 3;
            int c = (e & 7) * 4;
            float4 va = *reinterpret_cast<const float4*>(A + (size_t)r*SEQ + k0 + c);
            As[r][c+0] = wmma::__float_to_tf32(va.x);
            As[r][c+1] = wmma::__float_to_tf32(va.y);
            As[r][c+2] = wmma::__float_to_tf32(va.z);
            As[r][c+3] = wmma::__float_to_tf32(va.w);
            // B: 512 float4 slots (32x64)
            int rb = e >> 4;
            int cb = (e & 15) * 4;
            float4 vb = *reinterpret_cast<const float4*>(B + (size_t)(k0 + rb)*DH + cb);
            Bs[rb][cb+0] = wmma::__float_to_tf32(vb.x);
            Bs[rb][cb+1] = wmma::__float_to_tf32(vb.y);
            Bs[rb][cb+2] = wmma::__float_to_tf32(vb.z);
            Bs[rb][cb+3] = wmma::__float_to_tf32(vb.w);
        }
        __syncthreads();

        #pragma unroll
        for (int kf = 0; kf < 4; ++kf) {
            wmma::fragment<wmma::matrix_a, 16, 16, 8, wmma::precision::tf32, wmma::row_major> af[2];
            wmma::fragment<wmma::matrix_b, 16, 16, 8, wmma::precision::tf32, wmma::row_major> bf[2];
            #pragma unroll
            for (int mi = 0; mi < 2; ++mi)
                wmma::load_matrix_sync(af[mi], &As[wm*32 + mi*16][kf*8], 36);
            #pragma unroll
            for (int ni = 0; ni < 2; ++ni)
                wmma::load_matrix_sync(bf[ni], &Bs[kf*8][wn*32 + ni*16], 68);
            #pragma unroll
            for (int mi = 0; mi < 2; ++mi)
                #pragma unroll
                for (int ni = 0; ni < 2; ++ni)
                    wmma::mma_sync(cf[mi][ni], af[mi], bf[ni], cf[mi][ni]);
        }
        __syncthreads();
    }

    #pragma unroll
    for (int mi = 0; mi < 2; ++mi)
        #pragma unroll
        for (int ni = 0; ni < 2; ++ni)
            wmma::store_matrix_sync(
                C + (size_t)(wm*32 + mi*16)*DMODEL + (wn*32 + ni*16),
                cf[mi][ni], DMODEL, wmma::mem_row_major);
}

// ---------------------------------------------------------------------------
// bias add: out[r, c] += bo[c]
// ---------------------------------------------------------------------------
__global__ void bias_add(float* __restrict__ out, const float* __restrict__ bo)
{
    size_t idx = (size_t)blockIdx.x * 256 + threadIdx.x;   // 4 M elements
    out[idx] += bo[idx & (DMODEL - 1)];
}

// ---------------------------------------------------------------------------
extern "C" void kernel_launch(void* const* d_in, const int* in_sizes, int n_in,
                              void* d_out, int out_size)
{
    const float* x   = (const float*)d_in[0];
    const float* rel = (const float*)d_in[1];
    const float* Wq  = (const float*)d_in[2];
    const float* Wk  = (const float*)d_in[3];
    const float* Wv  = (const float*)d_in[4];
    const float* Wo  = (const float*)d_in[5];
    const float* bo  = (const float*)d_in[6];
    float* out = (float*)d_out;

    float *q, *k, *v, *s, *ctx;
    cudaGetSymbolAddress((void**)&q,   g_q);
    cudaGetSymbolAddress((void**)&k,   g_k);
    cudaGetSymbolAddress((void**)&v,   g_v);
    cudaGetSymbolAddress((void**)&s,   g_s);
    cudaGetSymbolAddress((void**)&ctx, g_ctx);

    // Projections: y = x @ W^T  (NT GEMMs, M = 4096)
    gemm_nt<<<dim3(64, 16), 128>>>(x, DMODEL, Wq, DMODEL, q, DMODEL, DMODEL);
    gemm_nt<<<dim3(64, 1 ), 128>>>(x, DMODEL, Wk, DMODEL, k, DH,     DMODEL);
    gemm_nt<<<dim3(64, 1 ), 128>>>(x, DMODEL, Wv, DMODEL, v, DH,     DMODEL);

    // scores = c2c, then += c2p
    c2c_kernel<<<dim3(16, 16, 64), 128>>>();
    c2p_kernel<<<dim3(16, 1024),  128>>>(rel);

    // softmax((c2c + c2p) / 8)
    softmax_kernel<<<8192, 256>>>();

    // context = attn @ v
    av_kernel<<<dim3(16, 1, 64), 128>>>();

    // out = ctx @ Wo^T + bo
    gemm_nt<<<dim3(64, 16), 128>>>(ctx, DMODEL, Wo, DMODEL, out, DMODEL, DMODEL);
    bias_add<<<16384, 256>>>(out, bo);
}